// round 11
// baseline (speedup 1.0000x reference)
#include <cuda_runtime.h>
#include <cstdint>

// inverse lifting wavelet: (16,256,128,128) f32 -> (16,64,256,256) f32
//
// Y1[b,c,g,h,w]  = in[b, g*64+c, h, w]
// s_g(h,w)       = M2[g,:] . Y1[b,c,:,h,w]
// Y3_i(h,w)      = M1[i,0]*s0(h,w) + M1[i,1]*s1(h-1,w)
//                + M1[i,2]*s2(h,w-1) + M1[i,3]*s3(h-1,w-1)   (indices wrap)
// out[b,c,2h+p,2w+q] = Y3_{2p+q}(h,w)
//
// R11: sustained-depth streaming. HT=16 strip through an NSTAGES=8 cp.async
// ring: one row issued per row consumed, so pending depth stays pinned at 7
// for most of the strip (avg ~6.1 rows in flight vs R10's ~4.5, +36% avg
// in-flight bytes, same smem/regs). Halo re-reads also halve (-16MB).

#define FULL 0xffffffffu

constexpr int H1 = 128, W1 = 128, C = 64;
constexpr int HT = 16;                      // rows per warp strip
constexpr int STAGE_BYTES = 4 * 32 * 16;    // 2048 B per row-stage
constexpr int NSTAGES = 8;
constexpr int WARPS_PER_BLK = 2;

__device__ __forceinline__ void cpa16(uint32_t saddr, const float* g) {
    asm volatile("cp.async.cg.shared.global [%0], [%1], 16;" :: "r"(saddr), "l"(g));
}
__device__ __forceinline__ void cpa_commit() {
    asm volatile("cp.async.commit_group;");
}
template <int N>
__device__ __forceinline__ void cpa_wait() {
    asm volatile("cp.async.wait_group %0;" :: "n"(N));
}
__device__ __forceinline__ void stcs4(float* p, float4 v) {
    __stcs((float4*)p, v);
}

// Consume prev raw row (pv*) + cur raw row (cv*) -> output rows 2h, 2h+1.
__device__ __forceinline__ void compute_store(
    const float4& pv0, const float4& pv1, const float4& pv2, const float4& pv3,
    const float4& cv0, const float4& cv1, const float4& cv2, const float4& cv3,
    float* __restrict__ outb, int h, int lane)
{
    float cg0[4] = {cv0.x, cv0.y, cv0.z, cv0.w};
    float cg1[4] = {cv1.x, cv1.y, cv1.z, cv1.w};
    float cg2[4] = {cv2.x, cv2.y, cv2.z, cv2.w};
    float cg3[4] = {cv3.x, cv3.y, cv3.z, cv3.w};
    float pg0[4] = {pv0.x, pv0.y, pv0.z, pv0.w};
    float pg1[4] = {pv1.x, pv1.y, pv1.z, pv1.w};
    float pg2[4] = {pv2.x, pv2.y, pv2.z, pv2.w};
    float pg3[4] = {pv3.x, pv3.y, pv3.z, pv3.w};

    float s0[4], s1[4], s2[4], s3[4];
    #pragma unroll
    for (int i = 0; i < 4; ++i) {
        // M2 rows 0,2 on current row; rows 1,3 on previous row
        s0[i] =  1.3968f * cg0[i] - 0.2212f * cg1[i] - 0.5412f * cg2[i] + 1.3066f * cg3[i];
        s2[i] = -0.2212f * cg0[i] - 1.3968f * cg1[i] - 1.3066f * cg2[i] - 0.5412f * cg3[i];
        s1[i] =  0.2212f * pg0[i] + 1.3968f * pg1[i] - 1.3066f * pg2[i] - 0.5412f * pg3[i];
        s3[i] = -1.3968f * pg0[i] + 0.2212f * pg1[i] - 0.5412f * pg2[i] + 1.3066f * pg3[i];
    }

    // w-1 values: circular shift across the warp (implements roll wrap at w=0)
    const int src = (lane + 31) & 31;
    float s2n = __shfl_sync(FULL, s2[3], src);
    float s3n = __shfl_sync(FULL, s3[3], src);
    float a2[4] = {s2n, s2[0], s2[1], s2[2]};
    float a3[4] = {s3n, s3[0], s3[1], s3[2]};

    float* rtop = outb + (size_t)(2 * h)     * 256 + 8 * lane;
    float* rbot = outb + (size_t)(2 * h + 1) * 256 + 8 * lane;

    // top row (Y3_0, Y3_1 interleaved) — compute+store first to cut live regs
    {
        float o0[4], o1[4];
        #pragma unroll
        for (int i = 0; i < 4; ++i) {
            o0[i] =  0.2166f * s0[i] - 0.0256f * s1[i] + 0.1213f * a2[i] + 0.0144f * a3[i];
            o1[i] =  0.0256f * s0[i] + 0.2166f * s1[i] + 0.0144f * a2[i] - 0.1213f * a3[i];
        }
        stcs4(rtop,     make_float4(o0[0], o1[0], o0[1], o1[1]));
        stcs4(rtop + 4, make_float4(o0[2], o1[2], o0[3], o1[3]));
    }
    // bottom row (Y3_2, Y3_3 interleaved)
    {
        float o2[4], o3[4];
        #pragma unroll
        for (int i = 0; i < 4; ++i) {
            o2[i] =  0.1213f * s0[i] - 0.0144f * s1[i] - 0.2166f * a2[i] - 0.0256f * a3[i];
            o3[i] = -0.0144f * s0[i] - 0.1213f * s1[i] + 0.0256f * a2[i] - 0.2166f * a3[i];
        }
        stcs4(rbot,     make_float4(o2[0], o3[0], o2[1], o3[1]));
        stcs4(rbot + 4, make_float4(o2[2], o3[2], o2[3], o3[3]));
    }
}

__global__ __launch_bounds__(WARPS_PER_BLK * 32, 7)
void inlwt_kernel(const float* __restrict__ in, float* __restrict__ out) {
    __shared__ __align__(16) char smem[WARPS_PER_BLK * NSTAGES * STAGE_BYTES];  // 32 KB

    const int tid  = threadIdx.x;
    const int wid  = tid >> 5;
    const int lane = tid & 31;
    const int gw   = (blockIdx.x * blockDim.x + tid) >> 5;   // 0..8191

    const int htile = gw & 7;
    const int cc    = (gw >> 3) & 63;
    const int b     = gw >> 9;

    const int h0 = htile * HT;
    const int w0 = lane * 4;

    const float* inb  = in  + (size_t)(b * 256 + cc) * (H1 * W1);
    float*       outb = out + (size_t)(b * C   + cc) * (size_t)(2 * H1) * (2 * W1);
    const size_t gs   = (size_t)64 * H1 * W1;   // channel-group stride

    char* wbase = smem + wid * (NSTAGES * STAGE_BYTES);
    const uint32_t sbase =
        (uint32_t)__cvta_generic_to_shared(wbase) + (uint32_t)(lane * 16);

    // issue one row (4 group-rows) into a stage; one commit-group per row
    auto issue = [&](int stage, int row) {
        const float* gp = inb + (size_t)row * W1 + w0;
        const uint32_t sp = sbase + stage * STAGE_BYTES;
        #pragma unroll
        for (int g = 0; g < 4; ++g)
            cpa16(sp + g * 512, gp + g * gs);
        cpa_commit();
    };
    // read one row-stage into registers (per-lane: reads back its own bytes)
    auto read_stage = [&](int stage, float4& v0, float4& v1, float4& v2, float4& v3) {
        const char* sp = wbase + stage * STAGE_BYTES + lane * 16;
        v0 = *(const float4*)(sp + 0 * 512);
        v1 = *(const float4*)(sp + 1 * 512);
        v2 = *(const float4*)(sp + 2 * 512);
        v3 = *(const float4*)(sp + 3 * 512);
    };

    // prologue: halo (stage 0) + rows h0..h0+6 (stages 1..7) = 8 groups
    const int hp = (h0 == 0) ? (H1 - 1) : (h0 - 1);
    issue(0, hp);
    #pragma unroll
    for (int k = 0; k < NSTAGES - 1; ++k)
        issue(k + 1, h0 + k);

    cpa_wait<NSTAGES - 1>();            // halo row landed
    float4 pv0, pv1, pv2, pv3;
    read_stage(0, pv0, pv1, pv2, pv3);

    // row h0+j lives in stage (j+1)%8; stage i%8 frees at iteration i.
    // Steady state (i = 0 .. HT-8): issue row h0+i+7, keep 7 groups pending.
    #pragma unroll 3
    for (int i = 0; i <= HT - NSTAGES; ++i) {
        issue(i & 7, h0 + i + NSTAGES - 1);
        cpa_wait<NSTAGES - 1>();        // row i ready, 7 pending

        float4 cv0, cv1, cv2, cv3;
        read_stage((i + 1) & 7, cv0, cv1, cv2, cv3);
        compute_store(pv0, pv1, pv2, pv3, cv0, cv1, cv2, cv3, outb, h0 + i, lane);
        pv0 = cv0; pv1 = cv1; pv2 = cv2; pv3 = cv3;
    }

    // drain: i = HT-7 .. HT-1, pending = HT-1-i
    #pragma unroll
    for (int i = HT - NSTAGES + 1; i < HT; ++i) {
        if      (i + 6 < HT) cpa_wait<6>();
        else if (i + 5 < HT) cpa_wait<5>();
        else if (i + 4 < HT) cpa_wait<4>();
        else if (i + 3 < HT) cpa_wait<3>();
        else if (i + 2 < HT) cpa_wait<2>();
        else if (i + 1 < HT) cpa_wait<1>();
        else                 cpa_wait<0>();

        float4 cv0, cv1, cv2, cv3;
        read_stage((i + 1) & 7, cv0, cv1, cv2, cv3);
        compute_store(pv0, pv1, pv2, pv3, cv0, cv1, cv2, cv3, outb, h0 + i, lane);
        pv0 = cv0; pv1 = cv1; pv2 = cv2; pv3 = cv3;
    }
}

extern "C" void kernel_launch(void* const* d_in, const int* in_sizes, int n_in,
                              void* d_out, int out_size) {
    const float* in = (const float*)d_in[0];
    float* out = (float*)d_out;
    // 16 b * 64 c * 8 htiles = 8192 warps; 2 warps per block -> 4096 blocks.
    inlwt_kernel<<<4096, 64>>>(in, out);
}

// round 12
// speedup vs baseline: 1.0286x; 1.0286x over previous
#include <cuda_runtime.h>
#include <cstdint>

// inverse lifting wavelet: (16,256,128,128) f32 -> (16,64,256,256) f32
//
// Y1[b,c,g,h,w]  = in[b, g*64+c, h, w]
// s_g(h,w)       = M2[g,:] . Y1[b,c,:,h,w]
// Y3_i(h,w)      = M1[i,0]*s0(h,w) + M1[i,1]*s1(h-1,w)
//                + M1[i,2]*s2(h,w-1) + M1[i,3]*s3(h-1,w-1)   (indices wrap)
// out[b,c,2h+p,2w+q] = Y3_{2p+q}(h,w)
//
// R12: R10 burst design (HT=8 strip fully burst-issued via cp.async, 2
// warps/block) with NSTAGES=7 -> 28KB smem/block -> 8 blocks/SM (16 warps,
// +14% concurrent bursts) and L2 evict-first policy on the streaming loads
// (read-once data shouldn't occupy L2 ways needed by store writeback).
// Lesson bank: HT=16 loses (R8,R11); drip-feed issue loses (R11);
// contiguous 8-row bursts win (R10).

#define FULL 0xffffffffu

constexpr int H1 = 128, W1 = 128, C = 64;
constexpr int HT = 8;                       // rows per warp strip
constexpr int STAGE_BYTES = 4 * 32 * 16;    // 2048 B per row-stage
constexpr int NSTAGES = 7;                  // halo + 6 rows buffered, 1 refill
constexpr int WARPS_PER_BLK = 2;

__device__ __forceinline__ void cpa16(uint32_t saddr, const float* g, uint64_t pol) {
    asm volatile("cp.async.cg.shared.global.L2::cache_hint [%0], [%1], 16, %2;"
                 :: "r"(saddr), "l"(g), "l"(pol));
}
__device__ __forceinline__ void cpa_commit() {
    asm volatile("cp.async.commit_group;");
}
template <int N>
__device__ __forceinline__ void cpa_wait() {
    asm volatile("cp.async.wait_group %0;" :: "n"(N));
}
__device__ __forceinline__ void stcs4(float* p, float4 v) {
    __stcs((float4*)p, v);
}

// Consume prev raw row (pv*) + cur raw row (cv*) -> output rows 2h, 2h+1.
__device__ __forceinline__ void compute_store(
    const float4& pv0, const float4& pv1, const float4& pv2, const float4& pv3,
    const float4& cv0, const float4& cv1, const float4& cv2, const float4& cv3,
    float* __restrict__ outb, int h, int lane)
{
    float cg0[4] = {cv0.x, cv0.y, cv0.z, cv0.w};
    float cg1[4] = {cv1.x, cv1.y, cv1.z, cv1.w};
    float cg2[4] = {cv2.x, cv2.y, cv2.z, cv2.w};
    float cg3[4] = {cv3.x, cv3.y, cv3.z, cv3.w};
    float pg0[4] = {pv0.x, pv0.y, pv0.z, pv0.w};
    float pg1[4] = {pv1.x, pv1.y, pv1.z, pv1.w};
    float pg2[4] = {pv2.x, pv2.y, pv2.z, pv2.w};
    float pg3[4] = {pv3.x, pv3.y, pv3.z, pv3.w};

    float s0[4], s1[4], s2[4], s3[4];
    #pragma unroll
    for (int i = 0; i < 4; ++i) {
        // M2 rows 0,2 on current row; rows 1,3 on previous row
        s0[i] =  1.3968f * cg0[i] - 0.2212f * cg1[i] - 0.5412f * cg2[i] + 1.3066f * cg3[i];
        s2[i] = -0.2212f * cg0[i] - 1.3968f * cg1[i] - 1.3066f * cg2[i] - 0.5412f * cg3[i];
        s1[i] =  0.2212f * pg0[i] + 1.3968f * pg1[i] - 1.3066f * pg2[i] - 0.5412f * pg3[i];
        s3[i] = -1.3968f * pg0[i] + 0.2212f * pg1[i] - 0.5412f * pg2[i] + 1.3066f * pg3[i];
    }

    // w-1 values: circular shift across the warp (implements roll wrap at w=0)
    const int src = (lane + 31) & 31;
    float s2n = __shfl_sync(FULL, s2[3], src);
    float s3n = __shfl_sync(FULL, s3[3], src);
    float a2[4] = {s2n, s2[0], s2[1], s2[2]};
    float a3[4] = {s3n, s3[0], s3[1], s3[2]};

    float* rtop = outb + (size_t)(2 * h)     * 256 + 8 * lane;
    float* rbot = outb + (size_t)(2 * h + 1) * 256 + 8 * lane;

    // top row (Y3_0, Y3_1 interleaved) — compute+store first to cut live regs
    {
        float o0[4], o1[4];
        #pragma unroll
        for (int i = 0; i < 4; ++i) {
            o0[i] =  0.2166f * s0[i] - 0.0256f * s1[i] + 0.1213f * a2[i] + 0.0144f * a3[i];
            o1[i] =  0.0256f * s0[i] + 0.2166f * s1[i] + 0.0144f * a2[i] - 0.1213f * a3[i];
        }
        stcs4(rtop,     make_float4(o0[0], o1[0], o0[1], o1[1]));
        stcs4(rtop + 4, make_float4(o0[2], o1[2], o0[3], o1[3]));
    }
    // bottom row (Y3_2, Y3_3 interleaved)
    {
        float o2[4], o3[4];
        #pragma unroll
        for (int i = 0; i < 4; ++i) {
            o2[i] =  0.1213f * s0[i] - 0.0144f * s1[i] - 0.2166f * a2[i] - 0.0256f * a3[i];
            o3[i] = -0.0144f * s0[i] - 0.1213f * s1[i] + 0.0256f * a2[i] - 0.2166f * a3[i];
        }
        stcs4(rbot,     make_float4(o2[0], o3[0], o2[1], o3[1]));
        stcs4(rbot + 4, make_float4(o2[2], o3[2], o2[3], o3[3]));
    }
}

__global__ __launch_bounds__(WARPS_PER_BLK * 32, 8)
void inlwt_kernel(const float* __restrict__ in, float* __restrict__ out) {
    __shared__ __align__(16) char smem[WARPS_PER_BLK * NSTAGES * STAGE_BYTES];  // 28 KB

    const int tid  = threadIdx.x;
    const int wid  = tid >> 5;
    const int lane = tid & 31;
    const int gw   = (blockIdx.x * blockDim.x + tid) >> 5;   // 0..16383

    const int htile = gw & 15;
    const int cc    = (gw >> 4) & 63;
    const int b     = gw >> 10;

    const int h0 = htile * HT;
    const int w0 = lane * 4;

    const float* inb  = in  + (size_t)(b * 256 + cc) * (H1 * W1);
    float*       outb = out + (size_t)(b * C   + cc) * (size_t)(2 * H1) * (2 * W1);
    const size_t gs   = (size_t)64 * H1 * W1;   // channel-group stride

    uint64_t pol;
    asm("createpolicy.fractional.L2::evict_first.b64 %0, 1.0;" : "=l"(pol));

    char* wbase = smem + wid * (NSTAGES * STAGE_BYTES);
    const uint32_t sbase =
        (uint32_t)__cvta_generic_to_shared(wbase) + (uint32_t)(lane * 16);

    // issue one row (4 group-rows) into a stage; one commit-group per row
    auto issue = [&](int stage, int row) {
        const float* gp = inb + (size_t)row * W1 + w0;
        const uint32_t sp = sbase + stage * STAGE_BYTES;
        #pragma unroll
        for (int g = 0; g < 4; ++g)
            cpa16(sp + g * 512, gp + g * gs, pol);
        cpa_commit();
    };
    // read one row-stage into registers (per-lane: reads back its own bytes)
    auto read_stage = [&](int stage, float4& v0, float4& v1, float4& v2, float4& v3) {
        const char* sp = wbase + stage * STAGE_BYTES + lane * 16;
        v0 = *(const float4*)(sp + 0 * 512);
        v1 = *(const float4*)(sp + 1 * 512);
        v2 = *(const float4*)(sp + 2 * 512);
        v3 = *(const float4*)(sp + 3 * 512);
    };

    // prologue: burst-issue halo + rows h0..h0+5 (7 stages, 28 LDGSTS)
    const int hp = (h0 == 0) ? (H1 - 1) : (h0 - 1);
    issue(0, hp);
    #pragma unroll
    for (int k = 0; k < NSTAGES - 1; ++k)
        issue(k + 1, h0 + k);

    cpa_wait<NSTAGES - 1>();            // halo row landed
    float4 pv0, pv1, pv2, pv3;
    read_stage(0, pv0, pv1, pv2, pv3);

    // row h0+j lives in stage (j+1)%7; stage (i%7) frees at iteration i
    #pragma unroll
    for (int i = 0; i < HT; ++i) {
        if (i + NSTAGES - 1 < HT)       // i=0,1: refill rows h0+6, h0+7
            issue(i % NSTAGES, h0 + i + NSTAGES - 1);

        // pending groups after row i completes = HT-1-i (rows i+1..HT-1)
        if      (i + 6 < HT) cpa_wait<6>();
        else if (i + 5 < HT) cpa_wait<5>();
        else if (i + 4 < HT) cpa_wait<4>();
        else if (i + 3 < HT) cpa_wait<3>();
        else if (i + 2 < HT) cpa_wait<2>();
        else if (i + 1 < HT) cpa_wait<1>();
        else                 cpa_wait<0>();

        float4 cv0, cv1, cv2, cv3;
        read_stage((i + 1) % NSTAGES, cv0, cv1, cv2, cv3);

        compute_store(pv0, pv1, pv2, pv3, cv0, cv1, cv2, cv3, outb, h0 + i, lane);

        pv0 = cv0; pv1 = cv1; pv2 = cv2; pv3 = cv3;
    }
}

extern "C" void kernel_launch(void* const* d_in, const int* in_sizes, int n_in,
                              void* d_out, int out_size) {
    const float* in = (const float*)d_in[0];
    float* out = (float*)d_out;
    // 16 b * 64 c * 16 htiles = 16384 warps; 2 warps per block -> 8192 blocks.
    inlwt_kernel<<<8192, 64>>>(in, out);
}

// round 13
// speedup vs baseline: 1.0290x; 1.0004x over previous
#include <cuda_runtime.h>
#include <cstdint>

// inverse lifting wavelet: (16,256,128,128) f32 -> (16,64,256,256) f32
//
// Y1[b,c,g,h,w]  = in[b, g*64+c, h, w]
// s_g(h,w)       = M2[g,:] . Y1[b,c,:,h,w]
// Y3_i(h,w)      = M1[i,0]*s0(h,w) + M1[i,1]*s1(h-1,w)
//                + M1[i,2]*s2(h,w-1) + M1[i,3]*s3(h-1,w-1)   (indices wrap)
// out[b,c,2h+p,2w+q] = Y3_{2p+q}(h,w)
//
// R13: exact R10 winner (HT=8 full-strip cp.async burst, NSTAGES=8,
// 2 warps/block, 7 blocks/SM) with ONE change: stores use the DEFAULT
// cache policy instead of __stcs (evict-first). Hypothesis: evict-first
// dirty lines force prompt, fine-grained writebacks that interleave with
// the read stream at DRAM (R/W turnaround penalty); default policy lets
// the 126MB L2 batch writebacks into longer bursts.

#define FULL 0xffffffffu

constexpr int H1 = 128, W1 = 128, C = 64;
constexpr int HT = 8;                       // rows per warp strip
constexpr int STAGE_BYTES = 4 * 32 * 16;    // 2048 B per row-stage
constexpr int NSTAGES = 8;
constexpr int WARPS_PER_BLK = 2;

__device__ __forceinline__ void cpa16(uint32_t saddr, const float* g) {
    asm volatile("cp.async.cg.shared.global [%0], [%1], 16;" :: "r"(saddr), "l"(g));
}
__device__ __forceinline__ void cpa_commit() {
    asm volatile("cp.async.commit_group;");
}
template <int N>
__device__ __forceinline__ void cpa_wait() {
    asm volatile("cp.async.wait_group %0;" :: "n"(N));
}
__device__ __forceinline__ void st4(float* p, float4 v) {
    *(float4*)p = v;                         // default cache policy
}

// Consume prev raw row (pv*) + cur raw row (cv*) -> output rows 2h, 2h+1.
__device__ __forceinline__ void compute_store(
    const float4& pv0, const float4& pv1, const float4& pv2, const float4& pv3,
    const float4& cv0, const float4& cv1, const float4& cv2, const float4& cv3,
    float* __restrict__ outb, int h, int lane)
{
    float cg0[4] = {cv0.x, cv0.y, cv0.z, cv0.w};
    float cg1[4] = {cv1.x, cv1.y, cv1.z, cv1.w};
    float cg2[4] = {cv2.x, cv2.y, cv2.z, cv2.w};
    float cg3[4] = {cv3.x, cv3.y, cv3.z, cv3.w};
    float pg0[4] = {pv0.x, pv0.y, pv0.z, pv0.w};
    float pg1[4] = {pv1.x, pv1.y, pv1.z, pv1.w};
    float pg2[4] = {pv2.x, pv2.y, pv2.z, pv2.w};
    float pg3[4] = {pv3.x, pv3.y, pv3.z, pv3.w};

    float s0[4], s1[4], s2[4], s3[4];
    #pragma unroll
    for (int i = 0; i < 4; ++i) {
        // M2 rows 0,2 on current row; rows 1,3 on previous row
        s0[i] =  1.3968f * cg0[i] - 0.2212f * cg1[i] - 0.5412f * cg2[i] + 1.3066f * cg3[i];
        s2[i] = -0.2212f * cg0[i] - 1.3968f * cg1[i] - 1.3066f * cg2[i] - 0.5412f * cg3[i];
        s1[i] =  0.2212f * pg0[i] + 1.3968f * pg1[i] - 1.3066f * pg2[i] - 0.5412f * pg3[i];
        s3[i] = -1.3968f * pg0[i] + 0.2212f * pg1[i] - 0.5412f * pg2[i] + 1.3066f * pg3[i];
    }

    // w-1 values: circular shift across the warp (implements roll wrap at w=0)
    const int src = (lane + 31) & 31;
    float s2n = __shfl_sync(FULL, s2[3], src);
    float s3n = __shfl_sync(FULL, s3[3], src);
    float a2[4] = {s2n, s2[0], s2[1], s2[2]};
    float a3[4] = {s3n, s3[0], s3[1], s3[2]};

    float* rtop = outb + (size_t)(2 * h)     * 256 + 8 * lane;
    float* rbot = outb + (size_t)(2 * h + 1) * 256 + 8 * lane;

    // top row (Y3_0, Y3_1 interleaved) — compute+store first to cut live regs
    {
        float o0[4], o1[4];
        #pragma unroll
        for (int i = 0; i < 4; ++i) {
            o0[i] =  0.2166f * s0[i] - 0.0256f * s1[i] + 0.1213f * a2[i] + 0.0144f * a3[i];
            o1[i] =  0.0256f * s0[i] + 0.2166f * s1[i] + 0.0144f * a2[i] - 0.1213f * a3[i];
        }
        st4(rtop,     make_float4(o0[0], o1[0], o0[1], o1[1]));
        st4(rtop + 4, make_float4(o0[2], o1[2], o0[3], o1[3]));
    }
    // bottom row (Y3_2, Y3_3 interleaved)
    {
        float o2[4], o3[4];
        #pragma unroll
        for (int i = 0; i < 4; ++i) {
            o2[i] =  0.1213f * s0[i] - 0.0144f * s1[i] - 0.2166f * a2[i] - 0.0256f * a3[i];
            o3[i] = -0.0144f * s0[i] - 0.1213f * s1[i] + 0.0256f * a2[i] - 0.2166f * a3[i];
        }
        st4(rbot,     make_float4(o2[0], o3[0], o2[1], o3[1]));
        st4(rbot + 4, make_float4(o2[2], o3[2], o2[3], o3[3]));
    }
}

__global__ __launch_bounds__(WARPS_PER_BLK * 32, 7)
void inlwt_kernel(const float* __restrict__ in, float* __restrict__ out) {
    __shared__ __align__(16) char smem[WARPS_PER_BLK * NSTAGES * STAGE_BYTES];  // 32 KB

    const int tid  = threadIdx.x;
    const int wid  = tid >> 5;
    const int lane = tid & 31;
    const int gw   = (blockIdx.x * blockDim.x + tid) >> 5;   // 0..16383

    const int htile = gw & 15;
    const int cc    = (gw >> 4) & 63;
    const int b     = gw >> 10;

    const int h0 = htile * HT;
    const int w0 = lane * 4;

    const float* inb  = in  + (size_t)(b * 256 + cc) * (H1 * W1);
    float*       outb = out + (size_t)(b * C   + cc) * (size_t)(2 * H1) * (2 * W1);
    const size_t gs   = (size_t)64 * H1 * W1;   // channel-group stride

    char* wbase = smem + wid * (NSTAGES * STAGE_BYTES);
    const uint32_t sbase =
        (uint32_t)__cvta_generic_to_shared(wbase) + (uint32_t)(lane * 16);

    // issue one row (4 group-rows) into a stage; one commit-group per row
    auto issue = [&](int stage, int row) {
        const float* gp = inb + (size_t)row * W1 + w0;
        const uint32_t sp = sbase + stage * STAGE_BYTES;
        #pragma unroll
        for (int g = 0; g < 4; ++g)
            cpa16(sp + g * 512, gp + g * gs);
        cpa_commit();
    };
    // read one row-stage into registers (per-lane: reads back its own bytes)
    auto read_stage = [&](int stage, float4& v0, float4& v1, float4& v2, float4& v3) {
        const char* sp = wbase + stage * STAGE_BYTES + lane * 16;
        v0 = *(const float4*)(sp + 0 * 512);
        v1 = *(const float4*)(sp + 1 * 512);
        v2 = *(const float4*)(sp + 2 * 512);
        v3 = *(const float4*)(sp + 3 * 512);
    };

    // prologue: burst-issue halo + rows h0..h0+6 (8 stages, 32 LDGSTS)
    const int hp = (h0 == 0) ? (H1 - 1) : (h0 - 1);
    issue(0, hp);
    #pragma unroll
    for (int k = 0; k < NSTAGES - 1; ++k)
        issue(k + 1, h0 + k);

    cpa_wait<NSTAGES - 1>();            // halo row landed
    float4 pv0, pv1, pv2, pv3;
    read_stage(0, pv0, pv1, pv2, pv3);

    // row h0+k lives in stage (k+1)%8; stage i%8 is free at iteration i
    #pragma unroll
    for (int i = 0; i < HT; ++i) {
        if (i + NSTAGES - 1 < HT)       // only i==0 for HT==NSTAGES: row h0+7
            issue(i % NSTAGES, h0 + i + NSTAGES - 1);

        // pending groups after row i's group = HT-1-i  (rows i+1..HT-1)
        if      (i + 7 < HT) cpa_wait<7>();
        else if (i + 6 < HT) cpa_wait<6>();
        else if (i + 5 < HT) cpa_wait<5>();
        else if (i + 4 < HT) cpa_wait<4>();
        else if (i + 3 < HT) cpa_wait<3>();
        else if (i + 2 < HT) cpa_wait<2>();
        else if (i + 1 < HT) cpa_wait<1>();
        else                 cpa_wait<0>();

        float4 cv0, cv1, cv2, cv3;
        read_stage((i + 1) % NSTAGES, cv0, cv1, cv2, cv3);

        compute_store(pv0, pv1, pv2, pv3, cv0, cv1, cv2, cv3, outb, h0 + i, lane);

        pv0 = cv0; pv1 = cv1; pv2 = cv2; pv3 = cv3;
    }
}

extern "C" void kernel_launch(void* const* d_in, const int* in_sizes, int n_in,
                              void* d_out, int out_size) {
    const float* in = (const float*)d_in[0];
    float* out = (float*)d_out;
    // 16 b * 64 c * 16 htiles = 16384 warps; 2 warps per block -> 8192 blocks.
    inlwt_kernel<<<8192, 64>>>(in, out);
}

// round 14
// speedup vs baseline: 1.0537x; 1.0240x over previous
#include <cuda_runtime.h>
#include <cstdint>

// inverse lifting wavelet: (16,256,128,128) f32 -> (16,64,256,256) f32
//
// Y1[b,c,g,h,w]  = in[b, g*64+c, h, w]
// s_g(h,w)       = M2[g,:] . Y1[b,c,:,h,w]
// Y3_i(h,w)      = M1[i,0]*s0(h,w) + M1[i,1]*s1(h-1,w)
//                + M1[i,2]*s2(h,w-1) + M1[i,3]*s3(h-1,w-1)   (indices wrap)
// out[b,c,2h+p,2w+q] = Y3_{2p+q}(h,w)
//
// R14: phase-separated full burst. NSTAGES=9 = halo+strip as ONE g-major
// contiguous burst (4.5KB sequential per group-plane, 36 LDGSTS, single
// commit), then single wait, then an uninterrupted 8-row compute+store
// drain. Per-warp read-phase / write-phase alternation + 12 staggered
// warps/SM; peak in-flight 216KB/SM. Halo folded into the contiguous
// stream (no separate re-fetch request). Default-policy stores (R13).

#define FULL 0xffffffffu

constexpr int H1 = 128, W1 = 128, C = 64;
constexpr int HT = 8;                       // rows per warp strip
constexpr int STAGE_BYTES = 4 * 32 * 16;    // 2048 B per row-stage
constexpr int NSTAGES = 9;                  // halo + 8 rows, all buffered
constexpr int WARPS_PER_BLK = 2;

__device__ __forceinline__ void cpa16(uint32_t saddr, const float* g) {
    asm volatile("cp.async.cg.shared.global [%0], [%1], 16;" :: "r"(saddr), "l"(g));
}
__device__ __forceinline__ void cpa_commit() {
    asm volatile("cp.async.commit_group;");
}
template <int N>
__device__ __forceinline__ void cpa_wait() {
    asm volatile("cp.async.wait_group %0;" :: "n"(N));
}
__device__ __forceinline__ void st4(float* p, float4 v) {
    *(float4*)p = v;                         // default cache policy
}

// Consume prev raw row (pv*) + cur raw row (cv*) -> output rows 2h, 2h+1.
__device__ __forceinline__ void compute_store(
    const float4& pv0, const float4& pv1, const float4& pv2, const float4& pv3,
    const float4& cv0, const float4& cv1, const float4& cv2, const float4& cv3,
    float* __restrict__ outb, int h, int lane)
{
    float cg0[4] = {cv0.x, cv0.y, cv0.z, cv0.w};
    float cg1[4] = {cv1.x, cv1.y, cv1.z, cv1.w};
    float cg2[4] = {cv2.x, cv2.y, cv2.z, cv2.w};
    float cg3[4] = {cv3.x, cv3.y, cv3.z, cv3.w};
    float pg0[4] = {pv0.x, pv0.y, pv0.z, pv0.w};
    float pg1[4] = {pv1.x, pv1.y, pv1.z, pv1.w};
    float pg2[4] = {pv2.x, pv2.y, pv2.z, pv2.w};
    float pg3[4] = {pv3.x, pv3.y, pv3.z, pv3.w};

    float s0[4], s1[4], s2[4], s3[4];
    #pragma unroll
    for (int i = 0; i < 4; ++i) {
        // M2 rows 0,2 on current row; rows 1,3 on previous row
        s0[i] =  1.3968f * cg0[i] - 0.2212f * cg1[i] - 0.5412f * cg2[i] + 1.3066f * cg3[i];
        s2[i] = -0.2212f * cg0[i] - 1.3968f * cg1[i] - 1.3066f * cg2[i] - 0.5412f * cg3[i];
        s1[i] =  0.2212f * pg0[i] + 1.3968f * pg1[i] - 1.3066f * pg2[i] - 0.5412f * pg3[i];
        s3[i] = -1.3968f * pg0[i] + 0.2212f * pg1[i] - 0.5412f * pg2[i] + 1.3066f * pg3[i];
    }

    // w-1 values: circular shift across the warp (implements roll wrap at w=0)
    const int src = (lane + 31) & 31;
    float s2n = __shfl_sync(FULL, s2[3], src);
    float s3n = __shfl_sync(FULL, s3[3], src);
    float a2[4] = {s2n, s2[0], s2[1], s2[2]};
    float a3[4] = {s3n, s3[0], s3[1], s3[2]};

    float* rtop = outb + (size_t)(2 * h)     * 256 + 8 * lane;
    float* rbot = outb + (size_t)(2 * h + 1) * 256 + 8 * lane;

    // top row (Y3_0, Y3_1 interleaved) — compute+store first to cut live regs
    {
        float o0[4], o1[4];
        #pragma unroll
        for (int i = 0; i < 4; ++i) {
            o0[i] =  0.2166f * s0[i] - 0.0256f * s1[i] + 0.1213f * a2[i] + 0.0144f * a3[i];
            o1[i] =  0.0256f * s0[i] + 0.2166f * s1[i] + 0.0144f * a2[i] - 0.1213f * a3[i];
        }
        st4(rtop,     make_float4(o0[0], o1[0], o0[1], o1[1]));
        st4(rtop + 4, make_float4(o0[2], o1[2], o0[3], o1[3]));
    }
    // bottom row (Y3_2, Y3_3 interleaved)
    {
        float o2[4], o3[4];
        #pragma unroll
        for (int i = 0; i < 4; ++i) {
            o2[i] =  0.1213f * s0[i] - 0.0144f * s1[i] - 0.2166f * a2[i] - 0.0256f * a3[i];
            o3[i] = -0.0144f * s0[i] - 0.1213f * s1[i] + 0.0256f * a2[i] - 0.2166f * a3[i];
        }
        st4(rbot,     make_float4(o2[0], o3[0], o2[1], o3[1]));
        st4(rbot + 4, make_float4(o2[2], o3[2], o2[3], o3[3]));
    }
}

__global__ __launch_bounds__(WARPS_PER_BLK * 32, 6)
void inlwt_kernel(const float* __restrict__ in, float* __restrict__ out) {
    __shared__ __align__(16) char smem[WARPS_PER_BLK * NSTAGES * STAGE_BYTES];  // 36 KB

    const int tid  = threadIdx.x;
    const int wid  = tid >> 5;
    const int lane = tid & 31;
    const int gw   = (blockIdx.x * blockDim.x + tid) >> 5;   // 0..16383

    const int htile = gw & 15;
    const int cc    = (gw >> 4) & 63;
    const int b     = gw >> 10;

    const int h0 = htile * HT;
    const int w0 = lane * 4;

    const float* inb  = in  + (size_t)(b * 256 + cc) * (H1 * W1);
    float*       outb = out + (size_t)(b * C   + cc) * (size_t)(2 * H1) * (2 * W1);
    const size_t gs   = (size_t)64 * H1 * W1;   // channel-group stride

    char* wbase = smem + wid * (NSTAGES * STAGE_BYTES);
    const uint32_t sbase =
        (uint32_t)__cvta_generic_to_shared(wbase) + (uint32_t)(lane * 16);

    // ---- read phase: one g-major burst of 36 LDGSTS, single commit ----
    // stage 0 = halo row (hp), stage s>=1 = row h0+s-1. For htile>0 the 9
    // rows are CONTIGUOUS in memory -> 4.5KB sequential stream per group.
    const int hp = (h0 == 0) ? (H1 - 1) : (h0 - 1);
    #pragma unroll
    for (int g = 0; g < 4; ++g) {
        const float* gp = inb + g * gs + w0;
        #pragma unroll
        for (int s = 0; s < NSTAGES; ++s) {
            const int row = (s == 0) ? hp : (h0 + s - 1);
            cpa16(sbase + s * STAGE_BYTES + g * 512, gp + (size_t)row * W1);
        }
    }
    cpa_commit();
    cpa_wait<0>();                       // whole strip + halo landed

    // read one row-stage into registers (per-lane: reads back its own bytes)
    auto read_stage = [&](int stage, float4& v0, float4& v1, float4& v2, float4& v3) {
        const char* sp = wbase + stage * STAGE_BYTES + lane * 16;
        v0 = *(const float4*)(sp + 0 * 512);
        v1 = *(const float4*)(sp + 1 * 512);
        v2 = *(const float4*)(sp + 2 * 512);
        v3 = *(const float4*)(sp + 3 * 512);
    };

    // ---- write phase: uninterrupted 8 row-pair drain ----
    float4 pv0, pv1, pv2, pv3;
    read_stage(0, pv0, pv1, pv2, pv3);

    #pragma unroll
    for (int i = 0; i < HT; ++i) {
        float4 cv0, cv1, cv2, cv3;
        read_stage(i + 1, cv0, cv1, cv2, cv3);

        compute_store(pv0, pv1, pv2, pv3, cv0, cv1, cv2, cv3, outb, h0 + i, lane);

        pv0 = cv0; pv1 = cv1; pv2 = cv2; pv3 = cv3;
    }
}

extern "C" void kernel_launch(void* const* d_in, const int* in_sizes, int n_in,
                              void* d_out, int out_size) {
    const float* in = (const float*)d_in[0];
    float* out = (float*)d_out;
    // 16 b * 64 c * 16 htiles = 16384 warps; 2 warps per block -> 8192 blocks.
    inlwt_kernel<<<8192, 64>>>(in, out);
}

// round 15
// speedup vs baseline: 1.0565x; 1.0027x over previous
#include <cuda_runtime.h>
#include <cstdint>

// inverse lifting wavelet: (16,256,128,128) f32 -> (16,64,256,256) f32
//
// Y1[b,c,g,h,w]  = in[b, g*64+c, h, w]
// s_g(h,w)       = M2[g,:] . Y1[b,c,:,h,w]
// Y3_i(h,w)      = M1[i,0]*s0(h,w) + M1[i,1]*s1(h-1,w)
//                + M1[i,2]*s2(h,w-1) + M1[i,3]*s3(h-1,w-1)   (indices wrap)
// out[b,c,2h+p,2w+q] = Y3_{2p+q}(h,w)
//
// R15: longer phase-separated bursts. HT=16 strip fully buffered
// (NSTAGES=17, 34KB/warp, 1 warp per 32-thread block): halo read-amp
// drops 9/8 -> 17/16 (-16MB reads) and each group-plane burst is 8.5KB
// contiguous (68 LDGSTS, ONE commit, ONE wait), then an uninterrupted
// 16-row compute+store drain. 6 blocks/SM -> 204KB/SM in flight during
// bursts (= R14) with only 6 warps. Prior HT=16 losses (R8 lookahead
// shortage, R11 drip-feed) don't apply to the full-buffer structure.

#define FULL 0xffffffffu

constexpr int H1 = 128, W1 = 128, C = 64;
constexpr int HT = 16;                      // rows per warp strip
constexpr int STAGE_BYTES = 4 * 32 * 16;    // 2048 B per row-stage
constexpr int NSTAGES = HT + 1;             // halo + 16 rows, all buffered
constexpr int WARPS_PER_BLK = 1;

__device__ __forceinline__ void cpa16(uint32_t saddr, const float* g) {
    asm volatile("cp.async.cg.shared.global [%0], [%1], 16;" :: "r"(saddr), "l"(g));
}
__device__ __forceinline__ void cpa_commit() {
    asm volatile("cp.async.commit_group;");
}
template <int N>
__device__ __forceinline__ void cpa_wait() {
    asm volatile("cp.async.wait_group %0;" :: "n"(N));
}
__device__ __forceinline__ void st4(float* p, float4 v) {
    *(float4*)p = v;                         // default cache policy
}

// Consume prev raw row (pv*) + cur raw row (cv*) -> output rows 2h, 2h+1.
__device__ __forceinline__ void compute_store(
    const float4& pv0, const float4& pv1, const float4& pv2, const float4& pv3,
    const float4& cv0, const float4& cv1, const float4& cv2, const float4& cv3,
    float* __restrict__ outb, int h, int lane)
{
    float cg0[4] = {cv0.x, cv0.y, cv0.z, cv0.w};
    float cg1[4] = {cv1.x, cv1.y, cv1.z, cv1.w};
    float cg2[4] = {cv2.x, cv2.y, cv2.z, cv2.w};
    float cg3[4] = {cv3.x, cv3.y, cv3.z, cv3.w};
    float pg0[4] = {pv0.x, pv0.y, pv0.z, pv0.w};
    float pg1[4] = {pv1.x, pv1.y, pv1.z, pv1.w};
    float pg2[4] = {pv2.x, pv2.y, pv2.z, pv2.w};
    float pg3[4] = {pv3.x, pv3.y, pv3.z, pv3.w};

    float s0[4], s1[4], s2[4], s3[4];
    #pragma unroll
    for (int i = 0; i < 4; ++i) {
        // M2 rows 0,2 on current row; rows 1,3 on previous row
        s0[i] =  1.3968f * cg0[i] - 0.2212f * cg1[i] - 0.5412f * cg2[i] + 1.3066f * cg3[i];
        s2[i] = -0.2212f * cg0[i] - 1.3968f * cg1[i] - 1.3066f * cg2[i] - 0.5412f * cg3[i];
        s1[i] =  0.2212f * pg0[i] + 1.3968f * pg1[i] - 1.3066f * pg2[i] - 0.5412f * pg3[i];
        s3[i] = -1.3968f * pg0[i] + 0.2212f * pg1[i] - 0.5412f * pg2[i] + 1.3066f * pg3[i];
    }

    // w-1 values: circular shift across the warp (implements roll wrap at w=0)
    const int src = (lane + 31) & 31;
    float s2n = __shfl_sync(FULL, s2[3], src);
    float s3n = __shfl_sync(FULL, s3[3], src);
    float a2[4] = {s2n, s2[0], s2[1], s2[2]};
    float a3[4] = {s3n, s3[0], s3[1], s3[2]};

    float* rtop = outb + (size_t)(2 * h)     * 256 + 8 * lane;
    float* rbot = outb + (size_t)(2 * h + 1) * 256 + 8 * lane;

    // top row (Y3_0, Y3_1 interleaved) — compute+store first to cut live regs
    {
        float o0[4], o1[4];
        #pragma unroll
        for (int i = 0; i < 4; ++i) {
            o0[i] =  0.2166f * s0[i] - 0.0256f * s1[i] + 0.1213f * a2[i] + 0.0144f * a3[i];
            o1[i] =  0.0256f * s0[i] + 0.2166f * s1[i] + 0.0144f * a2[i] - 0.1213f * a3[i];
        }
        st4(rtop,     make_float4(o0[0], o1[0], o0[1], o1[1]));
        st4(rtop + 4, make_float4(o0[2], o1[2], o0[3], o1[3]));
    }
    // bottom row (Y3_2, Y3_3 interleaved)
    {
        float o2[4], o3[4];
        #pragma unroll
        for (int i = 0; i < 4; ++i) {
            o2[i] =  0.1213f * s0[i] - 0.0144f * s1[i] - 0.2166f * a2[i] - 0.0256f * a3[i];
            o3[i] = -0.0144f * s0[i] - 0.1213f * s1[i] + 0.0256f * a2[i] - 0.2166f * a3[i];
        }
        st4(rbot,     make_float4(o2[0], o3[0], o2[1], o3[1]));
        st4(rbot + 4, make_float4(o2[2], o3[2], o2[3], o3[3]));
    }
}

__global__ __launch_bounds__(WARPS_PER_BLK * 32, 6)
void inlwt_kernel(const float* __restrict__ in, float* __restrict__ out) {
    __shared__ __align__(16) char smem[NSTAGES * STAGE_BYTES];  // 34 KB

    const int lane = threadIdx.x & 31;
    const int gw   = blockIdx.x;             // one warp per block, 0..8191

    const int htile = gw & 7;
    const int cc    = (gw >> 3) & 63;
    const int b     = gw >> 9;

    const int h0 = htile * HT;
    const int w0 = lane * 4;

    const float* inb  = in  + (size_t)(b * 256 + cc) * (H1 * W1);
    float*       outb = out + (size_t)(b * C   + cc) * (size_t)(2 * H1) * (2 * W1);
    const size_t gs   = (size_t)64 * H1 * W1;   // channel-group stride

    const uint32_t sbase =
        (uint32_t)__cvta_generic_to_shared(smem) + (uint32_t)(lane * 16);

    // ---- read phase: one g-major burst of 68 LDGSTS, single commit ----
    // stage 0 = halo row (hp), stage s>=1 = row h0+s-1. For htile>0 the 17
    // rows are CONTIGUOUS in memory -> 8.5KB sequential stream per group.
    const int hp = (h0 == 0) ? (H1 - 1) : (h0 - 1);
    #pragma unroll
    for (int g = 0; g < 4; ++g) {
        const float* gp = inb + g * gs + w0;
        #pragma unroll
        for (int s = 0; s < NSTAGES; ++s) {
            const int row = (s == 0) ? hp : (h0 + s - 1);
            cpa16(sbase + s * STAGE_BYTES + g * 512, gp + (size_t)row * W1);
        }
    }
    cpa_commit();
    cpa_wait<0>();                       // whole strip + halo landed

    // read one row-stage into registers (per-lane: reads back its own bytes)
    auto read_stage = [&](int stage, float4& v0, float4& v1, float4& v2, float4& v3) {
        const char* sp = smem + stage * STAGE_BYTES + lane * 16;
        v0 = *(const float4*)(sp + 0 * 512);
        v1 = *(const float4*)(sp + 1 * 512);
        v2 = *(const float4*)(sp + 2 * 512);
        v3 = *(const float4*)(sp + 3 * 512);
    };

    // ---- write phase: uninterrupted 16 row-pair drain ----
    float4 pv0, pv1, pv2, pv3;
    read_stage(0, pv0, pv1, pv2, pv3);

    #pragma unroll 4
    for (int i = 0; i < HT; ++i) {
        float4 cv0, cv1, cv2, cv3;
        read_stage(i + 1, cv0, cv1, cv2, cv3);

        compute_store(pv0, pv1, pv2, pv3, cv0, cv1, cv2, cv3, outb, h0 + i, lane);

        pv0 = cv0; pv1 = cv1; pv2 = cv2; pv3 = cv3;
    }
}

extern "C" void kernel_launch(void* const* d_in, const int* in_sizes, int n_in,
                              void* d_out, int out_size) {
    const float* in = (const float*)d_in[0];
    float* out = (float*)d_out;
    // 16 b * 64 c * 8 htiles = 8192 strips; 1 warp (32 threads) per block.
    inlwt_kernel<<<8192, 32>>>(in, out);
}